// round 1
// baseline (speedup 1.0000x reference)
#include <cuda_runtime.h>
#include <math.h>

// Problem dims (fixed by the dataset)
#define B   64
#define TE  1024
#define DE  1024
#define DD  1024
#define H   1024

// Scratch (allocation-free rule: __device__ globals)
__device__ float g_Wa[B * H];        // Wa[b,h] = dec[b]·Wa_w[h] + Wa_b[h]
__device__ float g_scores[B * TE];   // scores, then softmax weights in-place

// ---------------------------------------------------------------------------
// K1: Wa[b,h] = sum_d dec[b,d] * Wa_w[h,d] + Wa_b[h]
// Grid: 64 blocks, each handles 16 h-rows for ALL 64 batches.
// ---------------------------------------------------------------------------
__global__ void wa_kernel(const float* __restrict__ dec,
                          const float* __restrict__ Wa_w,
                          const float* __restrict__ Wa_b) {
    const int h0 = blockIdx.x * 16;
    const int tid = threadIdx.x;
    const int hl = tid >> 4;     // 0..15
    const int bl = tid & 15;     // 0..15

    __shared__ float sW[16][65];
    __shared__ float sD[64][65];

    float acc[4] = {0.f, 0.f, 0.f, 0.f};

    for (int d0 = 0; d0 < DD; d0 += 64) {
        __syncthreads();
        // load sW: 16 h x 64 d (1024 elems, 4/thread, coalesced)
        #pragma unroll
        for (int i = 0; i < 4; i++) {
            int l = tid + i * 256;
            int h = l >> 6, d = l & 63;
            sW[h][d] = Wa_w[(size_t)(h0 + h) * DD + d0 + d];
        }
        // load sD: 64 b x 64 d (4096 elems, 16/thread, coalesced)
        #pragma unroll
        for (int i = 0; i < 16; i++) {
            int l = tid + i * 256;
            int b = l >> 6, d = l & 63;
            sD[b][d] = dec[(size_t)b * DD + d0 + d];
        }
        __syncthreads();
        #pragma unroll 8
        for (int d = 0; d < 64; d++) {
            float w = sW[hl][d];
            #pragma unroll
            for (int i = 0; i < 4; i++)
                acc[i] += w * sD[bl + 16 * i][d];
        }
    }
    float bias = Wa_b[h0 + hl];
    #pragma unroll
    for (int i = 0; i < 4; i++)
        g_Wa[(size_t)(bl + 16 * i) * H + h0 + hl] = acc[i] + bias;
}

// ---------------------------------------------------------------------------
// K2: fused  Ua-GEMM + tanh + Va reduction -> scores[b,e]
//   score[b,e] = Vb + sum_h Va_w[h] * tanh( Wa[b,h] + Ua_b[h] + enc[b,e]·Ua_w[h] )
// Block: (e-tile 64) x (b). 256 threads = 16x16, 4x4 register tile.
// h tiled by 64 (16 tiles), d tiled by 32.
// ---------------------------------------------------------------------------
#define BM 64
#define BN 64
#define BK 32

__global__ void score_kernel(const float* __restrict__ enc,
                             const float* __restrict__ Ua_w,
                             const float* __restrict__ Ua_b,
                             const float* __restrict__ Va_w,
                             const float* __restrict__ Va_b) {
    const int b  = blockIdx.y;
    const int e0 = blockIdx.x * BM;
    const float* encB = enc + (size_t)b * TE * DE;

    __shared__ float As[BM][BK + 1];
    __shared__ float Bs[BN][BK + 1];
    __shared__ float wau[BN];   // Wa[b,h] + Ua_b[h]
    __shared__ float vaw[BN];   // Va_w[h]
    __shared__ float scoreacc[BM];

    const int tid = threadIdx.x;
    const int tx = tid & 15;    // h-group
    const int ty = tid >> 4;    // e-group

    float sacc[4] = {0.f, 0.f, 0.f, 0.f};

    for (int h0 = 0; h0 < H; h0 += BN) {
        __syncthreads();  // prior epilogue finished reading wau/vaw
        if (tid < BN) {
            wau[tid] = g_Wa[(size_t)b * H + h0 + tid] + Ua_b[h0 + tid];
            vaw[tid] = Va_w[h0 + tid];
        }

        float acc[4][4] = {};
        for (int d0 = 0; d0 < DE; d0 += BK) {
            __syncthreads();
            // load enc tile (64x32) and Ua_w tile (64x32); 8 elems each per thread
            #pragma unroll
            for (int i = 0; i < 8; i++) {
                int l = tid + i * 256;
                int r = l >> 5, d = l & 31;
                As[r][d] = encB[(size_t)(e0 + r) * DE + d0 + d];
                Bs[r][d] = Ua_w[(size_t)(h0 + r) * DE + d0 + d];
            }
            __syncthreads();
            #pragma unroll
            for (int k = 0; k < BK; k++) {
                float a[4], bb[4];
                #pragma unroll
                for (int i = 0; i < 4; i++) a[i]  = As[ty * 4 + i][k];
                #pragma unroll
                for (int j = 0; j < 4; j++) bb[j] = Bs[tx * 4 + j][k];
                #pragma unroll
                for (int i = 0; i < 4; i++)
                    #pragma unroll
                    for (int j = 0; j < 4; j++)
                        acc[i][j] += a[i] * bb[j];
            }
        }
        __syncthreads();  // acc done; wau/vaw visible
        // epilogue: tanh + Va-weighted reduce into per-row score accumulators
        #pragma unroll
        for (int i = 0; i < 4; i++) {
            #pragma unroll
            for (int j = 0; j < 4; j++) {
                int h = tx * 4 + j;
                float v = tanhf(acc[i][j] + wau[h]);
                sacc[i] += v * vaw[h];
            }
        }
    }

    // reduce sacc over the 16 tx lanes (half-warp segments share ty)
    #pragma unroll
    for (int i = 0; i < 4; i++) {
        float s = sacc[i];
        #pragma unroll
        for (int off = 8; off > 0; off >>= 1)
            s += __shfl_down_sync(0xffffffffu, s, off, 16);
        if (tx == 0) scoreacc[ty * 4 + i] = s;
    }
    __syncthreads();
    if (tid < BM)
        g_scores[(size_t)b * TE + e0 + tid] = scoreacc[tid] + Va_b[0];
}

// ---------------------------------------------------------------------------
// K3: softmax over Te per batch (in-place on g_scores)
// ---------------------------------------------------------------------------
__global__ void softmax_kernel() {
    const int b = blockIdx.x;
    const int tid = threadIdx.x;
    float* row = g_scores + (size_t)b * TE;
    __shared__ float red[256];

    float m = -1e30f;
    #pragma unroll
    for (int i = 0; i < 4; i++) m = fmaxf(m, row[tid + i * 256]);
    red[tid] = m;
    __syncthreads();
    for (int s = 128; s > 0; s >>= 1) {
        if (tid < s) red[tid] = fmaxf(red[tid], red[tid + s]);
        __syncthreads();
    }
    float M = red[0];
    __syncthreads();

    float vals[4];
    float sum = 0.f;
    #pragma unroll
    for (int i = 0; i < 4; i++) {
        vals[i] = expf(row[tid + i * 256] - M);
        sum += vals[i];
    }
    red[tid] = sum;
    __syncthreads();
    for (int s = 128; s > 0; s >>= 1) {
        if (tid < s) red[tid] += red[tid + s];
        __syncthreads();
    }
    float inv = 1.f / red[0];
    #pragma unroll
    for (int i = 0; i < 4; i++) row[tid + i * 256] = vals[i] * inv;
}

// ---------------------------------------------------------------------------
// K4: context[b,d] = sum_e w[b,e] * enc[b,e,d]
// Zero first (d_out is poisoned), then split-e accumulation with atomics.
// ---------------------------------------------------------------------------
__global__ void zero_kernel(float* __restrict__ out) {
    out[blockIdx.x * 256 + threadIdx.x] = 0.f;
}

__global__ void context_kernel(const float* __restrict__ enc,
                               float* __restrict__ out) {
    const int b  = blockIdx.x;
    const int ec = blockIdx.y;          // 8 chunks of 128 e-positions
    const int tid = threadIdx.x;

    __shared__ float ws[128];
    if (tid < 128) ws[tid] = g_scores[(size_t)b * TE + ec * 128 + tid];
    __syncthreads();

    const float* eb = enc + (size_t)b * TE * DE + (size_t)ec * 128 * DE;
    float acc[4] = {0.f, 0.f, 0.f, 0.f};
    for (int e = 0; e < 128; e++) {
        float we = ws[e];
        #pragma unroll
        for (int i = 0; i < 4; i++)
            acc[i] += we * eb[(size_t)e * DE + tid + i * 256];
    }
    #pragma unroll
    for (int i = 0; i < 4; i++)
        atomicAdd(&out[(size_t)b * DE + tid + i * 256], acc[i]);
}

// ---------------------------------------------------------------------------
extern "C" void kernel_launch(void* const* d_in, const int* in_sizes, int n_in,
                              void* d_out, int out_size) {
    const float* enc  = (const float*)d_in[0];  // [B,Te,De]
    const float* dec  = (const float*)d_in[1];  // [B,1,Dd]
    const float* Wa_w = (const float*)d_in[2];  // [H,Dd]
    const float* Wa_b = (const float*)d_in[3];  // [H]
    const float* Ua_w = (const float*)d_in[4];  // [H,De]
    const float* Ua_b = (const float*)d_in[5];  // [H]
    const float* Va_w = (const float*)d_in[6];  // [1,H]
    const float* Va_b = (const float*)d_in[7];  // [1]
    float* out = (float*)d_out;                 // [B,1,De]

    wa_kernel<<<64, 256>>>(dec, Wa_w, Wa_b);
    score_kernel<<<dim3(TE / BM, B), 256>>>(enc, Ua_w, Ua_b, Va_w, Va_b);
    softmax_kernel<<<B, 256>>>();
    zero_kernel<<<(B * DE) / 256, 256>>>(out);
    context_kernel<<<dim3(B, 8), 256>>>(enc, out);
}

// round 2
// speedup vs baseline: 2.4329x; 2.4329x over previous
#include <cuda_runtime.h>
#include <math.h>
#include <stdint.h>

// Problem dims (fixed by the dataset)
#define B   64
#define TE  1024
#define DE  1024
#define DD  1024
#define H   1024

// Scratch (allocation-free rule: __device__ globals)
__device__ float g_Wa[B * H];        // Wa[b,h] = dec[b]·Wa_w[h] + Wa_b[h]
__device__ float g_scores[B * TE];   // scores, then softmax weights in-place

__device__ __forceinline__ uint32_t f2tf32(float x) {
    uint32_t r;
    asm("cvt.rna.tf32.f32 %0, %1;" : "=r"(r) : "f"(x));
    return r;
}

// ---------------------------------------------------------------------------
// K1: Wa[b,h] = sum_d dec[b,d] * Wa_w[h,d] + Wa_b[h]   (tiny, fp32 SIMT)
// ---------------------------------------------------------------------------
__global__ void wa_kernel(const float* __restrict__ dec,
                          const float* __restrict__ Wa_w,
                          const float* __restrict__ Wa_b) {
    const int h0 = blockIdx.x * 16;
    const int tid = threadIdx.x;
    const int hl = tid >> 4;     // 0..15
    const int bl = tid & 15;     // 0..15

    __shared__ float sW[16][65];
    __shared__ float sD[64][65];

    float acc[4] = {0.f, 0.f, 0.f, 0.f};

    for (int d0 = 0; d0 < DD; d0 += 64) {
        __syncthreads();
        #pragma unroll
        for (int i = 0; i < 4; i++) {
            int l = tid + i * 256;
            int h = l >> 6, d = l & 63;
            sW[h][d] = Wa_w[(size_t)(h0 + h) * DD + d0 + d];
        }
        #pragma unroll
        for (int i = 0; i < 16; i++) {
            int l = tid + i * 256;
            int b = l >> 6, d = l & 63;
            sD[b][d] = dec[(size_t)b * DD + d0 + d];
        }
        __syncthreads();
        #pragma unroll 8
        for (int d = 0; d < 64; d++) {
            float w = sW[hl][d];
            #pragma unroll
            for (int i = 0; i < 4; i++)
                acc[i] += w * sD[bl + 16 * i][d];
        }
    }
    float bias = Wa_b[h0 + hl];
    #pragma unroll
    for (int i = 0; i < 4; i++)
        g_Wa[(size_t)(bl + 16 * i) * H + h0 + hl] = acc[i] + bias;
}

// ---------------------------------------------------------------------------
// K2: fused Ua-GEMM (tf32 tensor cores) + tanh + Va reduction -> scores[b,e]
//   score[b,e] = Vb + sum_h Va_w[h] * tanh( Wa[b,h] + Ua_b[h] + enc[b,e]·Ua_w[h] )
//
// Tile: BM=128 e-rows per CTA, h in 16 tiles of BN=64, BK=32.
// 8 warps = 4(m) x 2(n); warp tile m32 x n32 via mma.m16n8k8.tf32.
// Smem stride 36 floats => conflict-free fragment LDS.
// ---------------------------------------------------------------------------
#define BM 128
#define BN 64
#define BK 32
#define SSTR 36

__global__ __launch_bounds__(256, 2)
void score_kernel(const float* __restrict__ enc,
                  const float* __restrict__ Ua_w,
                  const float* __restrict__ Ua_b,
                  const float* __restrict__ Va_w,
                  const float* __restrict__ Va_b) {
    const int b  = blockIdx.y;
    const int e0 = blockIdx.x * BM;
    const float* encB = enc + (size_t)b * TE * DE;

    __shared__ uint32_t As[BM][SSTR];
    __shared__ uint32_t Bs[BN][SSTR];
    __shared__ float wau[BN];
    __shared__ float vaw[BN];
    __shared__ float scoreacc[BM];

    const int tid  = threadIdx.x;
    const int wid  = tid >> 5;
    const int lane = tid & 31;
    const int wm = wid & 3;      // warp row: rows wm*32 .. +31
    const int wn = wid >> 2;     // warp col: h cols wn*32 .. +31
    const int lq = lane >> 2;    // 0..7
    const int lr = lane & 3;     // 0..3

    if (tid < BM) scoreacc[tid] = 0.f;

    for (int h0 = 0; h0 < H; h0 += BN) {
        __syncthreads();   // previous epilogue done with wau/vaw/smem
        if (tid < BN) {
            wau[tid] = g_Wa[(size_t)b * H + h0 + tid] + Ua_b[h0 + tid];
            vaw[tid] = Va_w[h0 + tid];
        }

        float acc[2][4][4];
        #pragma unroll
        for (int m = 0; m < 2; m++)
            #pragma unroll
            for (int n = 0; n < 4; n++)
                #pragma unroll
                for (int r = 0; r < 4; r++)
                    acc[m][n][r] = 0.f;

        for (int d0 = 0; d0 < DE; d0 += BK) {
            __syncthreads();
            // As: 128 rows x 8 float4 = 1024 float4, 4 per thread
            #pragma unroll
            for (int i = 0; i < 4; i++) {
                int l = tid + i * 256;
                int r = l >> 3, c = (l & 7) * 4;
                float4 v = *(const float4*)&encB[(size_t)(e0 + r) * DE + d0 + c];
                As[r][c + 0] = f2tf32(v.x);
                As[r][c + 1] = f2tf32(v.y);
                As[r][c + 2] = f2tf32(v.z);
                As[r][c + 3] = f2tf32(v.w);
            }
            // Bs: 64 rows x 8 float4 = 512 float4, 2 per thread
            #pragma unroll
            for (int i = 0; i < 2; i++) {
                int l = tid + i * 256;
                int r = l >> 3, c = (l & 7) * 4;
                float4 v = *(const float4*)&Ua_w[(size_t)(h0 + r) * DE + d0 + c];
                Bs[r][c + 0] = f2tf32(v.x);
                Bs[r][c + 1] = f2tf32(v.y);
                Bs[r][c + 2] = f2tf32(v.z);
                Bs[r][c + 3] = f2tf32(v.w);
            }
            __syncthreads();

            #pragma unroll
            for (int k0 = 0; k0 < BK; k0 += 8) {
                uint32_t a[2][4], bb[4][2];
                #pragma unroll
                for (int m = 0; m < 2; m++) {
                    int ar = wm * 32 + m * 16 + lq;
                    a[m][0] = As[ar][k0 + lr];
                    a[m][1] = As[ar + 8][k0 + lr];
                    a[m][2] = As[ar][k0 + lr + 4];
                    a[m][3] = As[ar + 8][k0 + lr + 4];
                }
                #pragma unroll
                for (int n = 0; n < 4; n++) {
                    int bn = wn * 32 + n * 8 + lq;
                    bb[n][0] = Bs[bn][k0 + lr];
                    bb[n][1] = Bs[bn][k0 + lr + 4];
                }
                #pragma unroll
                for (int m = 0; m < 2; m++)
                    #pragma unroll
                    for (int n = 0; n < 4; n++)
                        asm volatile(
                            "mma.sync.aligned.m16n8k8.row.col.f32.tf32.tf32.f32 "
                            "{%0,%1,%2,%3}, {%4,%5,%6,%7}, {%8,%9}, {%0,%1,%2,%3};\n"
                            : "+f"(acc[m][n][0]), "+f"(acc[m][n][1]),
                              "+f"(acc[m][n][2]), "+f"(acc[m][n][3])
                            : "r"(a[m][0]), "r"(a[m][1]), "r"(a[m][2]), "r"(a[m][3]),
                              "r"(bb[n][0]), "r"(bb[n][1]));
            }
        }
        __syncthreads();   // acc done; wau/vaw visible to all

        // epilogue: tanh + Va-weighted reduce into per-row score accumulators
        float rs[2][2] = {{0.f, 0.f}, {0.f, 0.f}};
        #pragma unroll
        for (int m = 0; m < 2; m++)
            #pragma unroll
            for (int n = 0; n < 4; n++)
                #pragma unroll
                for (int r = 0; r < 4; r++) {
                    int h = wn * 32 + n * 8 + 2 * lr + (r & 1);
                    float v = tanhf(acc[m][n][r] + wau[h]) * vaw[h];
                    rs[m][r >> 1] += v;
                }
        #pragma unroll
        for (int m = 0; m < 2; m++)
            #pragma unroll
            for (int hh = 0; hh < 2; hh++) {
                float s = rs[m][hh];
                s += __shfl_xor_sync(0xffffffffu, s, 1);
                s += __shfl_xor_sync(0xffffffffu, s, 2);
                if (lr == 0) {
                    int row = wm * 32 + m * 16 + hh * 8 + lq;
                    atomicAdd(&scoreacc[row], s);
                }
            }
    }

    __syncthreads();
    if (tid < BM)
        g_scores[(size_t)b * TE + e0 + tid] = scoreacc[tid] + Va_b[0];
}

// ---------------------------------------------------------------------------
// K3: softmax over Te per batch (in-place on g_scores)
// ---------------------------------------------------------------------------
__global__ void softmax_kernel() {
    const int b = blockIdx.x;
    const int tid = threadIdx.x;
    float* row = g_scores + (size_t)b * TE;
    __shared__ float red[256];

    float m = -1e30f;
    #pragma unroll
    for (int i = 0; i < 4; i++) m = fmaxf(m, row[tid + i * 256]);
    red[tid] = m;
    __syncthreads();
    for (int s = 128; s > 0; s >>= 1) {
        if (tid < s) red[tid] = fmaxf(red[tid], red[tid + s]);
        __syncthreads();
    }
    float M = red[0];
    __syncthreads();

    float vals[4];
    float sum = 0.f;
    #pragma unroll
    for (int i = 0; i < 4; i++) {
        vals[i] = expf(row[tid + i * 256] - M);
        sum += vals[i];
    }
    red[tid] = sum;
    __syncthreads();
    for (int s = 128; s > 0; s >>= 1) {
        if (tid < s) red[tid] += red[tid + s];
        __syncthreads();
    }
    float inv = 1.f / red[0];
    #pragma unroll
    for (int i = 0; i < 4; i++) row[tid + i * 256] = vals[i] * inv;
}

// ---------------------------------------------------------------------------
// K4: context[b,d] = sum_e w[b,e] * enc[b,e,d]
// ---------------------------------------------------------------------------
__global__ void zero_kernel(float* __restrict__ out) {
    out[blockIdx.x * 256 + threadIdx.x] = 0.f;
}

__global__ void context_kernel(const float* __restrict__ enc,
                               float* __restrict__ out) {
    const int b  = blockIdx.x;
    const int ec = blockIdx.y;          // 8 chunks of 128 e-positions
    const int tid = threadIdx.x;

    __shared__ float ws[128];
    if (tid < 128) ws[tid] = g_scores[(size_t)b * TE + ec * 128 + tid];
    __syncthreads();

    const float* eb = enc + (size_t)b * TE * DE + (size_t)ec * 128 * DE;
    float acc[4] = {0.f, 0.f, 0.f, 0.f};
    for (int e = 0; e < 128; e++) {
        float we = ws[e];
        #pragma unroll
        for (int i = 0; i < 4; i++)
            acc[i] += we * eb[(size_t)e * DE + tid + i * 256];
    }
    #pragma unroll
    for (int i = 0; i < 4; i++)
        atomicAdd(&out[(size_t)b * DE + tid + i * 256], acc[i]);
}

// ---------------------------------------------------------------------------
extern "C" void kernel_launch(void* const* d_in, const int* in_sizes, int n_in,
                              void* d_out, int out_size) {
    const float* enc  = (const float*)d_in[0];  // [B,Te,De]
    const float* dec  = (const float*)d_in[1];  // [B,1,Dd]
    const float* Wa_w = (const float*)d_in[2];  // [H,Dd]
    const float* Wa_b = (const float*)d_in[3];  // [H]
    const float* Ua_w = (const float*)d_in[4];  // [H,De]
    const float* Ua_b = (const float*)d_in[5];  // [H]
    const float* Va_w = (const float*)d_in[6];  // [1,H]
    const float* Va_b = (const float*)d_in[7];  // [1]
    float* out = (float*)d_out;                 // [B,1,De]

    wa_kernel<<<64, 256>>>(dec, Wa_w, Wa_b);
    score_kernel<<<dim3(TE / BM, B), 256>>>(enc, Ua_w, Ua_b, Va_w, Va_b);
    softmax_kernel<<<B, 256>>>();
    zero_kernel<<<(B * DE) / 256, 256>>>(out);
    context_kernel<<<dim3(B, 8), 256>>>(enc, out);
}

// round 5
// speedup vs baseline: 4.2714x; 1.7557x over previous
#include <cuda_runtime.h>
#include <math.h>
#include <stdint.h>

#define B   64
#define TE  1024
#define DE  1024
#define DD  1024
#define H   1024

__device__ float g_Wa[B * H];        // Wa[b,h] = dec[b]·Wa_w[h] + Wa_b[h]
__device__ float g_scores[B * TE];   // partial scores -> softmax weights

__device__ __forceinline__ void cp16(uint32_t s, const void* g) {
    asm volatile("cp.async.cg.shared.global [%0], [%1], 16;"
                 :: "r"(s), "l"(__cvta_generic_to_global(g)) : "memory");
}
#define CP_COMMIT() asm volatile("cp.async.commit_group;" ::: "memory")
#define CP_WAIT1()  asm volatile("cp.async.wait_group 1;" ::: "memory")
#define CP_WAIT0()  asm volatile("cp.async.wait_group 0;" ::: "memory")

__device__ __forceinline__ uint32_t smem_u32(const void* p) {
    uint32_t a;
    asm("{ .reg .u64 t; cvta.to.shared.u64 t, %1; cvt.u32.u64 %0, t; }" : "=r"(a) : "l"(p));
    return a;
}

// ---------------------------------------------------------------------------
// K0: zero partial-score accumulator
// ---------------------------------------------------------------------------
__global__ void zero_scores_kernel() {
    g_scores[blockIdx.x * 1024 + threadIdx.x] = 0.f;
}

// ---------------------------------------------------------------------------
// K1: Wa[b,h] = dec[b]·Wa_w[h] + Wa_b[h]   (tiny, fp32 SIMT)
// ---------------------------------------------------------------------------
__global__ void wa_kernel(const float* __restrict__ dec,
                          const float* __restrict__ Wa_w,
                          const float* __restrict__ Wa_b) {
    const int h0 = blockIdx.x * 16;
    const int tid = threadIdx.x;
    const int hl = tid >> 4;
    const int bl = tid & 15;

    __shared__ float sW[16][65];
    __shared__ float sD[64][65];

    float acc[4] = {0.f, 0.f, 0.f, 0.f};

    for (int d0 = 0; d0 < DD; d0 += 64) {
        __syncthreads();
        #pragma unroll
        for (int i = 0; i < 4; i++) {
            int l = tid + i * 256;
            int h = l >> 6, d = l & 63;
            sW[h][d] = Wa_w[(size_t)(h0 + h) * DD + d0 + d];
        }
        #pragma unroll
        for (int i = 0; i < 16; i++) {
            int l = tid + i * 256;
            int b = l >> 6, d = l & 63;
            sD[b][d] = dec[(size_t)b * DD + d0 + d];
        }
        __syncthreads();
        #pragma unroll 8
        for (int d = 0; d < 64; d++) {
            float w = sW[hl][d];
            #pragma unroll
            for (int i = 0; i < 4; i++)
                acc[i] += w * sD[bl + 16 * i][d];
        }
    }
    float bias = Wa_b[h0 + hl];
    #pragma unroll
    for (int i = 0; i < 4; i++)
        g_Wa[(size_t)(bl + 16 * i) * H + h0 + hl] = acc[i] + bias;
}

// ---------------------------------------------------------------------------
// K2: fused Ua-GEMM (mma.sync tf32, cp.async double-buffered) + tanh + Va
//   CTA tile: 128 e-rows x 128 h-cols, K=1024 in 32 chunks of 32.
//   8 warps = 4(m) x 2(n), warp tile m32 x n64, mma.m16n8k8.tf32.
//   Smem row stride 36 floats: conflict-free frag LDS, 16B-aligned cp.async.
// ---------------------------------------------------------------------------
#define SSTR 36
#define ABUF 18432              // 128*36*4 bytes per buffer
#define S_B  36864              // after 2 A buffers
#define S_WAU 73728
#define S_VAW 74240
#define SC_SMEM 74752

__global__ __launch_bounds__(256, 2)
void score_kernel(const float* __restrict__ enc,
                  const float* __restrict__ Ua_w,
                  const float* __restrict__ Ua_b,
                  const float* __restrict__ Va_w) {
    extern __shared__ char sm[];
    const uint32_t smb = smem_u32(sm);

    const int tid  = threadIdx.x;
    const int wid  = tid >> 5;
    const int lane = tid & 31;
    const int wm = wid & 3;       // warp rows: wm*32..+31
    const int wn = wid >> 1 >> 1; // wid>>2: warp cols: wn*64..+63
    const int lq = lane >> 2;     // 0..7
    const int lr = lane & 3;      // 0..3

    const int b  = blockIdx.y >> 3;
    const int e0 = (blockIdx.y & 7) * 128;
    const int h0 = blockIdx.x * 128;

    const char* gA = (const char*)(enc  + ((size_t)b * TE + e0) * DE);
    const char* gB = (const char*)(Ua_w + (size_t)h0 * DE);

    // per-thread load geometry: 4 rows apart by 32, 16B column chunk
    const int r0 = tid >> 3;
    const int cfB = (tid & 7) * 16;          // byte offset within 128B row
    uint32_t soff[4];
    #pragma unroll
    for (int i = 0; i < 4; i++)
        soff[i] = (uint32_t)(r0 + 32 * i) * (SSTR * 4) + cfB + (cfB >> 3);
    // note: (row*36 + cf)*4 = row*144 + cf*4; cf*4 = cfB... compute directly:
    #pragma unroll
    for (int i = 0; i < 4; i++)
        soff[i] = (uint32_t)(r0 + 32 * i) * 144 + cfB;

    const char* gAt = gA + (size_t)r0 * 4096 + cfB;
    const char* gBt = gB + (size_t)r0 * 4096 + cfB;

    // prologue: chunk 0 -> buf 0
    #pragma unroll
    for (int i = 0; i < 4; i++) {
        cp16(smb + soff[i],       gAt + (size_t)i * 32 * 4096);
        cp16(smb + S_B + soff[i], gBt + (size_t)i * 32 * 4096);
    }
    CP_COMMIT();

    float acc[2][8][4];
    #pragma unroll
    for (int m = 0; m < 2; m++)
        #pragma unroll
        for (int n = 0; n < 8; n++)
            #pragma unroll
            for (int r = 0; r < 4; r++)
                acc[m][n][r] = 0.f;

    for (int c = 0; c < 32; c++) {
        const int buf = c & 1;
        if (c + 1 < 32) {
            const uint32_t da = smb + (uint32_t)(buf ^ 1) * ABUF;
            const uint32_t db = smb + S_B + (uint32_t)(buf ^ 1) * ABUF;
            const size_t go = (size_t)(c + 1) * 128;
            #pragma unroll
            for (int i = 0; i < 4; i++) {
                cp16(da + soff[i], gAt + (size_t)i * 32 * 4096 + go);
                cp16(db + soff[i], gBt + (size_t)i * 32 * 4096 + go);
            }
            CP_COMMIT();
            CP_WAIT1();
        } else {
            CP_WAIT0();
        }
        __syncthreads();

        const uint32_t* As = (const uint32_t*)(sm + buf * ABUF);
        const uint32_t* Bs = (const uint32_t*)(sm + S_B + buf * ABUF);

        #pragma unroll
        for (int k0 = 0; k0 < 32; k0 += 8) {
            uint32_t a[2][4], bb[8][2];
            #pragma unroll
            for (int m = 0; m < 2; m++) {
                int ar = (wm * 32 + m * 16 + lq) * SSTR;
                a[m][0] = As[ar + k0 + lr];
                a[m][1] = As[ar + 8 * SSTR + k0 + lr];
                a[m][2] = As[ar + k0 + lr + 4];
                a[m][3] = As[ar + 8 * SSTR + k0 + lr + 4];
            }
            #pragma unroll
            for (int n = 0; n < 8; n++) {
                int bn = (wn * 64 + n * 8 + lq) * SSTR;
                bb[n][0] = Bs[bn + k0 + lr];
                bb[n][1] = Bs[bn + k0 + lr + 4];
            }
            #pragma unroll
            for (int m = 0; m < 2; m++)
                #pragma unroll
                for (int n = 0; n < 8; n++)
                    asm volatile(
                        "mma.sync.aligned.m16n8k8.row.col.f32.tf32.tf32.f32 "
                        "{%0,%1,%2,%3}, {%4,%5,%6,%7}, {%8,%9}, {%0,%1,%2,%3};\n"
                        : "+f"(acc[m][n][0]), "+f"(acc[m][n][1]),
                          "+f"(acc[m][n][2]), "+f"(acc[m][n][3])
                        : "r"(a[m][0]), "r"(a[m][1]), "r"(a[m][2]), "r"(a[m][3]),
                          "r"(bb[n][0]), "r"(bb[n][1]));
        }
        __syncthreads();
    }

    // stage wau/vaw for this h-block
    if (tid < 128) {
        ((float*)(sm + S_WAU))[tid] = g_Wa[(size_t)b * H + h0 + tid] + Ua_b[h0 + tid];
        ((float*)(sm + S_VAW))[tid] = Va_w[h0 + tid];
    }
    __syncthreads();
    const float* wau = (const float*)(sm + S_WAU);
    const float* vaw = (const float*)(sm + S_VAW);

    // epilogue: tanh + Va-weighted reduce -> per-row partial scores
    float rs[2][2] = {{0.f, 0.f}, {0.f, 0.f}};
    #pragma unroll
    for (int m = 0; m < 2; m++)
        #pragma unroll
        for (int n = 0; n < 8; n++)
            #pragma unroll
            for (int r = 0; r < 4; r++) {
                int h = wn * 64 + n * 8 + 2 * lr + (r & 1);
                rs[m][r >> 1] += vaw[h] * tanhf(acc[m][n][r] + wau[h]);
            }
    #pragma unroll
    for (int m = 0; m < 2; m++)
        #pragma unroll
        for (int rr = 0; rr < 2; rr++) {
            float s = rs[m][rr];
            s += __shfl_xor_sync(0xffffffffu, s, 1);
            s += __shfl_xor_sync(0xffffffffu, s, 2);
            if (lr == 0) {
                int e = e0 + wm * 32 + m * 16 + rr * 8 + lq;
                atomicAdd(&g_scores[(size_t)b * TE + e], s);
            }
        }
}

// ---------------------------------------------------------------------------
// K3: softmax over Te per batch (Va_b omitted: softmax shift-invariant)
// ---------------------------------------------------------------------------
__global__ void softmax_kernel() {
    const int b = blockIdx.x;
    const int tid = threadIdx.x;
    float* row = g_scores + (size_t)b * TE;
    __shared__ float red[256];

    float m = -1e30f;
    #pragma unroll
    for (int i = 0; i < 4; i++) m = fmaxf(m, row[tid + i * 256]);
    red[tid] = m;
    __syncthreads();
    for (int s = 128; s > 0; s >>= 1) {
        if (tid < s) red[tid] = fmaxf(red[tid], red[tid + s]);
        __syncthreads();
    }
    float M = red[0];
    __syncthreads();

    float vals[4];
    float sum = 0.f;
    #pragma unroll
    for (int i = 0; i < 4; i++) {
        vals[i] = expf(row[tid + i * 256] - M);
        sum += vals[i];
    }
    red[tid] = sum;
    __syncthreads();
    for (int s = 128; s > 0; s >>= 1) {
        if (tid < s) red[tid] += red[tid + s];
        __syncthreads();
    }
    float inv = 1.f / red[0];
    #pragma unroll
    for (int i = 0; i < 4; i++) row[tid + i * 256] = vals[i] * inv;
}

// ---------------------------------------------------------------------------
// K4: context[b,d] = sum_e w[b,e] * enc[b,e,d]
// ---------------------------------------------------------------------------
__global__ void zero_kernel(float* __restrict__ out) {
    out[blockIdx.x * 256 + threadIdx.x] = 0.f;
}

__global__ void context_kernel(const float* __restrict__ enc,
                               float* __restrict__ out) {
    const int b  = blockIdx.x;
    const int ec = blockIdx.y;
    const int tid = threadIdx.x;

    __shared__ float ws[128];
    if (tid < 128) ws[tid] = g_scores[(size_t)b * TE + ec * 128 + tid];
    __syncthreads();

    const float* eb = enc + (size_t)b * TE * DE + (size_t)ec * 128 * DE;
    float acc[4] = {0.f, 0.f, 0.f, 0.f};
    for (int e = 0; e < 128; e++) {
        float we = ws[e];
        #pragma unroll
        for (int i = 0; i < 4; i++)
            acc[i] += we * eb[(size_t)e * DE + tid + i * 256];
    }
    #pragma unroll
    for (int i = 0; i < 4; i++)
        atomicAdd(&out[(size_t)b * DE + tid + i * 256], acc[i]);
}

// ---------------------------------------------------------------------------
extern "C" void kernel_launch(void* const* d_in, const int* in_sizes, int n_in,
                              void* d_out, int out_size) {
    const float* enc  = (const float*)d_in[0];
    const float* dec  = (const float*)d_in[1];
    const float* Wa_w = (const float*)d_in[2];
    const float* Wa_b = (const float*)d_in[3];
    const float* Ua_w = (const float*)d_in[4];
    const float* Ua_b = (const float*)d_in[5];
    const float* Va_w = (const float*)d_in[6];
    float* out = (float*)d_out;

    cudaFuncSetAttribute(score_kernel, cudaFuncAttributeMaxDynamicSharedMemorySize, SC_SMEM);

    zero_scores_kernel<<<64, 1024>>>();
    wa_kernel<<<64, 256>>>(dec, Wa_w, Wa_b);
    score_kernel<<<dim3(H / 128, B * TE / 128), 256, SC_SMEM>>>(enc, Ua_w, Ua_b, Va_w);
    softmax_kernel<<<B, 256>>>();
    zero_kernel<<<(B * DE) / 256, 256>>>(out);
    context_kernel<<<dim3(B, 8), 256>>>(enc, out);
}

// round 6
// speedup vs baseline: 4.3984x; 1.0297x over previous
#include <cuda_runtime.h>
#include <math.h>
#include <stdint.h>

#define B   64
#define TE  1024
#define DE  1024
#define DD  1024
#define H   1024

__device__ float g_Wa[B * H];        // Wa[b,h] = dec[b]·Wa_w[h] + Wa_b[h]
__device__ float g_scores[B * TE];   // partial scores -> softmax weights

__device__ __forceinline__ void cp16(uint32_t s, const void* g) {
    asm volatile("cp.async.cg.shared.global [%0], [%1], 16;"
                 :: "r"(s), "l"(__cvta_generic_to_global(g)) : "memory");
}
#define CP_COMMIT() asm volatile("cp.async.commit_group;" ::: "memory")
#define CP_WAIT1()  asm volatile("cp.async.wait_group 1;" ::: "memory")
#define CP_WAIT0()  asm volatile("cp.async.wait_group 0;" ::: "memory")

__device__ __forceinline__ uint32_t smem_u32(const void* p) {
    uint32_t a;
    asm("{ .reg .u64 t; cvta.to.shared.u64 t, %1; cvt.u32.u64 %0, t; }" : "=r"(a) : "l"(p));
    return a;
}

// ---------------------------------------------------------------------------
// K0: zero partial-score accumulator
// ---------------------------------------------------------------------------
__global__ void zero_scores_kernel() {
    g_scores[blockIdx.x * 1024 + threadIdx.x] = 0.f;
}

// ---------------------------------------------------------------------------
// K1: Wa[b,h] = dec[b]·Wa_w[h] + Wa_b[h]   (tiny, fp32 SIMT)
// ---------------------------------------------------------------------------
__global__ void wa_kernel(const float* __restrict__ dec,
                          const float* __restrict__ Wa_w,
                          const float* __restrict__ Wa_b) {
    const int h0 = blockIdx.x * 16;
    const int tid = threadIdx.x;
    const int hl = tid >> 4;
    const int bl = tid & 15;

    __shared__ float sW[16][65];
    __shared__ float sD[64][65];

    float acc[4] = {0.f, 0.f, 0.f, 0.f};

    for (int d0 = 0; d0 < DD; d0 += 64) {
        __syncthreads();
        #pragma unroll
        for (int i = 0; i < 4; i++) {
            int l = tid + i * 256;
            int h = l >> 6, d = l & 63;
            sW[h][d] = Wa_w[(size_t)(h0 + h) * DD + d0 + d];
        }
        #pragma unroll
        for (int i = 0; i < 16; i++) {
            int l = tid + i * 256;
            int b = l >> 6, d = l & 63;
            sD[b][d] = dec[(size_t)b * DD + d0 + d];
        }
        __syncthreads();
        #pragma unroll 8
        for (int d = 0; d < 64; d++) {
            float w = sW[hl][d];
            #pragma unroll
            for (int i = 0; i < 4; i++)
                acc[i] += w * sD[bl + 16 * i][d];
        }
    }
    float bias = Wa_b[h0 + hl];
    #pragma unroll
    for (int i = 0; i < 4; i++)
        g_Wa[(size_t)(bl + 16 * i) * H + h0 + hl] = acc[i] + bias;
}

// ---------------------------------------------------------------------------
// K2: fused Ua-GEMM (mma.sync tf32) + tanh + Va reduction
//   CTA tile: 128 e x 128 h, K=1024 in 32 chunks of 32.
//   4 warps (128 threads) as 2(m) x 2(n); warp tile m64 x n64.
//   Per k8-step: 32 LDS.32 feed 32 HMMA -> 8 MAC/smem-byte (smem no longer
//   co-binding with the tensor pipe).
// ---------------------------------------------------------------------------
#define SSTR 36
#define ABUF 18432              // 128*36*4 bytes per buffer
#define S_B  36864
#define S_WAU 73728
#define S_VAW 74240
#define SC_SMEM 74752

__global__ __launch_bounds__(128, 2)
void score_kernel(const float* __restrict__ enc,
                  const float* __restrict__ Ua_w,
                  const float* __restrict__ Ua_b,
                  const float* __restrict__ Va_w) {
    extern __shared__ char sm[];
    const uint32_t smb = smem_u32(sm);

    const int tid  = threadIdx.x;
    const int wid  = tid >> 5;
    const int lane = tid & 31;
    const int wm = wid >> 1;      // warp rows: wm*64..+63
    const int wn = wid & 1;       // warp cols: wn*64..+63
    const int lq = lane >> 2;     // 0..7
    const int lr = lane & 3;      // 0..3

    const int b  = blockIdx.y >> 3;
    const int e0 = (blockIdx.y & 7) * 128;
    const int h0 = blockIdx.x * 128;

    const char* gA = (const char*)(enc  + ((size_t)b * TE + e0) * DE);
    const char* gB = (const char*)(Ua_w + (size_t)h0 * DE);

    // load geometry: 128 threads cover 128 rows x 32 floats (8 rows/thread)
    const int r0 = tid >> 3;               // 0..15
    const int cfB = (tid & 7) * 16;        // byte offset in 128B row-chunk
    uint32_t soff[8];
    #pragma unroll
    for (int i = 0; i < 8; i++)
        soff[i] = (uint32_t)(r0 + 16 * i) * 144 + cfB;

    const char* gAt = gA + (size_t)r0 * 4096 + cfB;
    const char* gBt = gB + (size_t)r0 * 4096 + cfB;

    // prologue: chunk 0 -> buf 0
    #pragma unroll
    for (int i = 0; i < 8; i++) {
        cp16(smb + soff[i],       gAt + (size_t)i * 16 * 4096);
        cp16(smb + S_B + soff[i], gBt + (size_t)i * 16 * 4096);
    }
    CP_COMMIT();

    float acc[4][8][4];
    #pragma unroll
    for (int m = 0; m < 4; m++)
        #pragma unroll
        for (int n = 0; n < 8; n++)
            #pragma unroll
            for (int r = 0; r < 4; r++)
                acc[m][n][r] = 0.f;

    for (int c = 0; c < 32; c++) {
        const int buf = c & 1;
        if (c + 1 < 32) {
            const uint32_t da = smb + (uint32_t)(buf ^ 1) * ABUF;
            const uint32_t db = smb + S_B + (uint32_t)(buf ^ 1) * ABUF;
            const size_t go = (size_t)(c + 1) * 128;
            #pragma unroll
            for (int i = 0; i < 8; i++) {
                cp16(da + soff[i], gAt + (size_t)i * 16 * 4096 + go);
                cp16(db + soff[i], gBt + (size_t)i * 16 * 4096 + go);
            }
            CP_COMMIT();
            CP_WAIT1();
        } else {
            CP_WAIT0();
        }
        __syncthreads();

        const uint32_t* As = (const uint32_t*)(sm + buf * ABUF);
        const uint32_t* Bs = (const uint32_t*)(sm + S_B + buf * ABUF);

        #pragma unroll
        for (int k0 = 0; k0 < 32; k0 += 8) {
            uint32_t a[4][4], bb[8][2];
            #pragma unroll
            for (int m = 0; m < 4; m++) {
                int ar = (wm * 64 + m * 16 + lq) * SSTR;
                a[m][0] = As[ar + k0 + lr];
                a[m][1] = As[ar + 8 * SSTR + k0 + lr];
                a[m][2] = As[ar + k0 + lr + 4];
                a[m][3] = As[ar + 8 * SSTR + k0 + lr + 4];
            }
            #pragma unroll
            for (int n = 0; n < 8; n++) {
                int bn = (wn * 64 + n * 8 + lq) * SSTR;
                bb[n][0] = Bs[bn + k0 + lr];
                bb[n][1] = Bs[bn + k0 + lr + 4];
            }
            #pragma unroll
            for (int m = 0; m < 4; m++)
                #pragma unroll
                for (int n = 0; n < 8; n++)
                    asm volatile(
                        "mma.sync.aligned.m16n8k8.row.col.f32.tf32.tf32.f32 "
                        "{%0,%1,%2,%3}, {%4,%5,%6,%7}, {%8,%9}, {%0,%1,%2,%3};\n"
                        : "+f"(acc[m][n][0]), "+f"(acc[m][n][1]),
                          "+f"(acc[m][n][2]), "+f"(acc[m][n][3])
                        : "r"(a[m][0]), "r"(a[m][1]), "r"(a[m][2]), "r"(a[m][3]),
                          "r"(bb[n][0]), "r"(bb[n][1]));
        }
        __syncthreads();
    }

    // stage wau/vaw for this h-block
    ((float*)(sm + S_WAU))[tid] = g_Wa[(size_t)b * H + h0 + tid] + Ua_b[h0 + tid];
    ((float*)(sm + S_VAW))[tid] = Va_w[h0 + tid];
    __syncthreads();
    const float* wau = (const float*)(sm + S_WAU);
    const float* vaw = (const float*)(sm + S_VAW);

    // epilogue: tanh + Va-weighted reduce -> per-row partial scores
    #pragma unroll
    for (int m = 0; m < 4; m++) {
        float rs[2] = {0.f, 0.f};
        #pragma unroll
        for (int n = 0; n < 8; n++)
            #pragma unroll
            for (int r = 0; r < 4; r++) {
                int h = wn * 64 + n * 8 + 2 * lr + (r & 1);
                rs[r >> 1] += vaw[h] * tanhf(acc[m][n][r] + wau[h]);
            }
        #pragma unroll
        for (int rr = 0; rr < 2; rr++) {
            float s = rs[rr];
            s += __shfl_xor_sync(0xffffffffu, s, 1);
            s += __shfl_xor_sync(0xffffffffu, s, 2);
            if (lr == 0) {
                int e = e0 + wm * 64 + m * 16 + rr * 8 + lq;
                atomicAdd(&g_scores[(size_t)b * TE + e], s);
            }
        }
    }
}

// ---------------------------------------------------------------------------
// K3: softmax over Te per batch (Va_b omitted: softmax shift-invariant)
// ---------------------------------------------------------------------------
__global__ void softmax_kernel() {
    const int b = blockIdx.x;
    const int tid = threadIdx.x;
    float* row = g_scores + (size_t)b * TE;
    __shared__ float red[256];

    float m = -1e30f;
    #pragma unroll
    for (int i = 0; i < 4; i++) m = fmaxf(m, row[tid + i * 256]);
    red[tid] = m;
    __syncthreads();
    for (int s = 128; s > 0; s >>= 1) {
        if (tid < s) red[tid] = fmaxf(red[tid], red[tid + s]);
        __syncthreads();
    }
    float M = red[0];
    __syncthreads();

    float vals[4];
    float sum = 0.f;
    #pragma unroll
    for (int i = 0; i < 4; i++) {
        vals[i] = expf(row[tid + i * 256] - M);
        sum += vals[i];
    }
    red[tid] = sum;
    __syncthreads();
    for (int s = 128; s > 0; s >>= 1) {
        if (tid < s) red[tid] += red[tid + s];
        __syncthreads();
    }
    float inv = 1.f / red[0];
    #pragma unroll
    for (int i = 0; i < 4; i++) row[tid + i * 256] = vals[i] * inv;
}

// ---------------------------------------------------------------------------
// K4: context[b,d] = sum_e w[b,e] * enc[b,e,d]
// ---------------------------------------------------------------------------
__global__ void zero_kernel(float* __restrict__ out) {
    out[blockIdx.x * 256 + threadIdx.x] = 0.f;
}

__global__ void context_kernel(const float* __restrict__ enc,
                               float* __restrict__ out) {
    const int b  = blockIdx.x;
    const int ec = blockIdx.y;
    const int tid = threadIdx.x;

    __shared__ float ws[128];
    if (tid < 128) ws[tid] = g_scores[(size_t)b * TE + ec * 128 + tid];
    __syncthreads();

    const float* eb = enc + (size_t)b * TE * DE + (size_t)ec * 128 * DE;
    float acc[4] = {0.f, 0.f, 0.f, 0.f};
    for (int e = 0; e < 128; e++) {
        float we = ws[e];
        #pragma unroll
        for (int i = 0; i < 4; i++)
            acc[i] += we * eb[(size_t)e * DE + tid + i * 256];
    }
    #pragma unroll
    for (int i = 0; i < 4; i++)
        atomicAdd(&out[(size_t)b * DE + tid + i * 256], acc[i]);
}

// ---------------------------------------------------------------------------
extern "C" void kernel_launch(void* const* d_in, const int* in_sizes, int n_in,
                              void* d_out, int out_size) {
    const float* enc  = (const float*)d_in[0];
    const float* dec  = (const float*)d_in[1];
    const float* Wa_w = (const float*)d_in[2];
    const float* Wa_b = (const float*)d_in[3];
    const float* Ua_w = (const float*)d_in[4];
    const float* Ua_b = (const float*)d_in[5];
    const float* Va_w = (const float*)d_in[6];
    float* out = (float*)d_out;

    cudaFuncSetAttribute(score_kernel, cudaFuncAttributeMaxDynamicSharedMemorySize, SC_SMEM);

    zero_scores_kernel<<<64, 1024>>>();
    wa_kernel<<<64, 256>>>(dec, Wa_w, Wa_b);
    score_kernel<<<dim3(H / 128, B * TE / 128), 128, SC_SMEM>>>(enc, Ua_w, Ua_b, Va_w);
    softmax_kernel<<<B, 256>>>();
    zero_kernel<<<(B * DE) / 256, 256>>>(out);
    context_kernel<<<dim3(B, 8), 256>>>(enc, out);
}

// round 7
// speedup vs baseline: 4.3985x; 1.0000x over previous
#include <cuda_runtime.h>
#include <math.h>
#include <stdint.h>

#define B   64
#define TE  1024
#define DE  1024
#define DD  1024
#define H   1024

__device__ float g_Wa[B * H];        // Wa[b,h] = dec[b]·Wa_w[h] + Wa_b[h]
__device__ float g_scores[B * TE];   // partial scores -> softmax weights

__device__ __forceinline__ void cp16(uint32_t s, const void* g) {
    asm volatile("cp.async.cg.shared.global [%0], [%1], 16;"
                 :: "r"(s), "l"(__cvta_generic_to_global(g)) : "memory");
}
#define CP_COMMIT() asm volatile("cp.async.commit_group;" ::: "memory")
#define CP_WAIT1()  asm volatile("cp.async.wait_group 1;" ::: "memory")
#define CP_WAIT0()  asm volatile("cp.async.wait_group 0;" ::: "memory")

__device__ __forceinline__ uint32_t smem_u32(const void* p) {
    uint32_t a;
    asm("{ .reg .u64 t; cvta.to.shared.u64 t, %1; cvt.u32.u64 %0, t; }" : "=r"(a) : "l"(p));
    return a;
}

// ---------------------------------------------------------------------------
// K0: zero partial-score accumulator
// ---------------------------------------------------------------------------
__global__ void zero_scores_kernel() {
    g_scores[blockIdx.x * 1024 + threadIdx.x] = 0.f;
}

// ---------------------------------------------------------------------------
// K1: Wa[b,h] = dec[b]·Wa_w[h] + Wa_b[h]   (tiny, fp32 SIMT)
// ---------------------------------------------------------------------------
__global__ void wa_kernel(const float* __restrict__ dec,
                          const float* __restrict__ Wa_w,
                          const float* __restrict__ Wa_b) {
    const int h0 = blockIdx.x * 16;
    const int tid = threadIdx.x;
    const int hl = tid >> 4;
    const int bl = tid & 15;

    __shared__ float sW[16][65];
    __shared__ float sD[64][65];

    float acc[4] = {0.f, 0.f, 0.f, 0.f};

    for (int d0 = 0; d0 < DD; d0 += 64) {
        __syncthreads();
        #pragma unroll
        for (int i = 0; i < 4; i++) {
            int l = tid + i * 256;
            int h = l >> 6, d = l & 63;
            sW[h][d] = Wa_w[(size_t)(h0 + h) * DD + d0 + d];
        }
        #pragma unroll
        for (int i = 0; i < 16; i++) {
            int l = tid + i * 256;
            int b = l >> 6, d = l & 63;
            sD[b][d] = dec[(size_t)b * DD + d0 + d];
        }
        __syncthreads();
        #pragma unroll 8
        for (int d = 0; d < 64; d++) {
            float w = sW[hl][d];
            #pragma unroll
            for (int i = 0; i < 4; i++)
                acc[i] += w * sD[bl + 16 * i][d];
        }
    }
    float bias = Wa_b[h0 + hl];
    #pragma unroll
    for (int i = 0; i < 4; i++)
        g_Wa[(size_t)(bl + 16 * i) * H + h0 + hl] = acc[i] + bias;
}

// ---------------------------------------------------------------------------
// K2: fused Ua-GEMM (mma.sync tf32) + tanh + Va reduction
//   CTA tile: 128 e x 128 h, K=1024 in 32 chunks of 32.
//   4 warps (128 threads) as 2(m) x 2(n); warp tile m64 x n64.
//   Per k8-step: 32 LDS.32 feed 32 HMMA -> 8 MAC/smem-byte (smem no longer
//   co-binding with the tensor pipe).
// ---------------------------------------------------------------------------
#define SSTR 36
#define ABUF 18432              // 128*36*4 bytes per buffer
#define S_B  36864
#define S_WAU 73728
#define S_VAW 74240
#define SC_SMEM 74752

__global__ __launch_bounds__(128, 2)
void score_kernel(const float* __restrict__ enc,
                  const float* __restrict__ Ua_w,
                  const float* __restrict__ Ua_b,
                  const float* __restrict__ Va_w) {
    extern __shared__ char sm[];
    const uint32_t smb = smem_u32(sm);

    const int tid  = threadIdx.x;
    const int wid  = tid >> 5;
    const int lane = tid & 31;
    const int wm = wid >> 1;      // warp rows: wm*64..+63
    const int wn = wid & 1;       // warp cols: wn*64..+63
    const int lq = lane >> 2;     // 0..7
    const int lr = lane & 3;      // 0..3

    const int b  = blockIdx.y >> 3;
    const int e0 = (blockIdx.y & 7) * 128;
    const int h0 = blockIdx.x * 128;

    const char* gA = (const char*)(enc  + ((size_t)b * TE + e0) * DE);
    const char* gB = (const char*)(Ua_w + (size_t)h0 * DE);

    // load geometry: 128 threads cover 128 rows x 32 floats (8 rows/thread)
    const int r0 = tid >> 3;               // 0..15
    const int cfB = (tid & 7) * 16;        // byte offset in 128B row-chunk
    uint32_t soff[8];
    #pragma unroll
    for (int i = 0; i < 8; i++)
        soff[i] = (uint32_t)(r0 + 16 * i) * 144 + cfB;

    const char* gAt = gA + (size_t)r0 * 4096 + cfB;
    const char* gBt = gB + (size_t)r0 * 4096 + cfB;

    // prologue: chunk 0 -> buf 0
    #pragma unroll
    for (int i = 0; i < 8; i++) {
        cp16(smb + soff[i],       gAt + (size_t)i * 16 * 4096);
        cp16(smb + S_B + soff[i], gBt + (size_t)i * 16 * 4096);
    }
    CP_COMMIT();

    float acc[4][8][4];
    #pragma unroll
    for (int m = 0; m < 4; m++)
        #pragma unroll
        for (int n = 0; n < 8; n++)
            #pragma unroll
            for (int r = 0; r < 4; r++)
                acc[m][n][r] = 0.f;

    for (int c = 0; c < 32; c++) {
        const int buf = c & 1;
        if (c + 1 < 32) {
            const uint32_t da = smb + (uint32_t)(buf ^ 1) * ABUF;
            const uint32_t db = smb + S_B + (uint32_t)(buf ^ 1) * ABUF;
            const size_t go = (size_t)(c + 1) * 128;
            #pragma unroll
            for (int i = 0; i < 8; i++) {
                cp16(da + soff[i], gAt + (size_t)i * 16 * 4096 + go);
                cp16(db + soff[i], gBt + (size_t)i * 16 * 4096 + go);
            }
            CP_COMMIT();
            CP_WAIT1();
        } else {
            CP_WAIT0();
        }
        __syncthreads();

        const uint32_t* As = (const uint32_t*)(sm + buf * ABUF);
        const uint32_t* Bs = (const uint32_t*)(sm + S_B + buf * ABUF);

        #pragma unroll
        for (int k0 = 0; k0 < 32; k0 += 8) {
            uint32_t a[4][4], bb[8][2];
            #pragma unroll
            for (int m = 0; m < 4; m++) {
                int ar = (wm * 64 + m * 16 + lq) * SSTR;
                a[m][0] = As[ar + k0 + lr];
                a[m][1] = As[ar + 8 * SSTR + k0 + lr];
                a[m][2] = As[ar + k0 + lr + 4];
                a[m][3] = As[ar + 8 * SSTR + k0 + lr + 4];
            }
            #pragma unroll
            for (int n = 0; n < 8; n++) {
                int bn = (wn * 64 + n * 8 + lq) * SSTR;
                bb[n][0] = Bs[bn + k0 + lr];
                bb[n][1] = Bs[bn + k0 + lr + 4];
            }
            #pragma unroll
            for (int m = 0; m < 4; m++)
                #pragma unroll
                for (int n = 0; n < 8; n++)
                    asm volatile(
                        "mma.sync.aligned.m16n8k8.row.col.f32.tf32.tf32.f32 "
                        "{%0,%1,%2,%3}, {%4,%5,%6,%7}, {%8,%9}, {%0,%1,%2,%3};\n"
                        : "+f"(acc[m][n][0]), "+f"(acc[m][n][1]),
                          "+f"(acc[m][n][2]), "+f"(acc[m][n][3])
                        : "r"(a[m][0]), "r"(a[m][1]), "r"(a[m][2]), "r"(a[m][3]),
                          "r"(bb[n][0]), "r"(bb[n][1]));
        }
        __syncthreads();
    }

    // stage wau/vaw for this h-block
    ((float*)(sm + S_WAU))[tid] = g_Wa[(size_t)b * H + h0 + tid] + Ua_b[h0 + tid];
    ((float*)(sm + S_VAW))[tid] = Va_w[h0 + tid];
    __syncthreads();
    const float* wau = (const float*)(sm + S_WAU);
    const float* vaw = (const float*)(sm + S_VAW);

    // epilogue: tanh + Va-weighted reduce -> per-row partial scores
    #pragma unroll
    for (int m = 0; m < 4; m++) {
        float rs[2] = {0.f, 0.f};
        #pragma unroll
        for (int n = 0; n < 8; n++)
            #pragma unroll
            for (int r = 0; r < 4; r++) {
                int h = wn * 64 + n * 8 + 2 * lr + (r & 1);
                rs[r >> 1] += vaw[h] * tanhf(acc[m][n][r] + wau[h]);
            }
        #pragma unroll
        for (int rr = 0; rr < 2; rr++) {
            float s = rs[rr];
            s += __shfl_xor_sync(0xffffffffu, s, 1);
            s += __shfl_xor_sync(0xffffffffu, s, 2);
            if (lr == 0) {
                int e = e0 + wm * 64 + m * 16 + rr * 8 + lq;
                atomicAdd(&g_scores[(size_t)b * TE + e], s);
            }
        }
    }
}

// ---------------------------------------------------------------------------
// K3: softmax over Te per batch (Va_b omitted: softmax shift-invariant)
// ---------------------------------------------------------------------------
__global__ void softmax_kernel() {
    const int b = blockIdx.x;
    const int tid = threadIdx.x;
    float* row = g_scores + (size_t)b * TE;
    __shared__ float red[256];

    float m = -1e30f;
    #pragma unroll
    for (int i = 0; i < 4; i++) m = fmaxf(m, row[tid + i * 256]);
    red[tid] = m;
    __syncthreads();
    for (int s = 128; s > 0; s >>= 1) {
        if (tid < s) red[tid] = fmaxf(red[tid], red[tid + s]);
        __syncthreads();
    }
    float M = red[0];
    __syncthreads();

    float vals[4];
    float sum = 0.f;
    #pragma unroll
    for (int i = 0; i < 4; i++) {
        vals[i] = expf(row[tid + i * 256] - M);
        sum += vals[i];
    }
    red[tid] = sum;
    __syncthreads();
    for (int s = 128; s > 0; s >>= 1) {
        if (tid < s) red[tid] += red[tid + s];
        __syncthreads();
    }
    float inv = 1.f / red[0];
    #pragma unroll
    for (int i = 0; i < 4; i++) row[tid + i * 256] = vals[i] * inv;
}

// ---------------------------------------------------------------------------
// K4: context[b,d] = sum_e w[b,e] * enc[b,e,d]
// ---------------------------------------------------------------------------
__global__ void zero_kernel(float* __restrict__ out) {
    out[blockIdx.x * 256 + threadIdx.x] = 0.f;
}

__global__ void context_kernel(const float* __restrict__ enc,
                               float* __restrict__ out) {
    const int b  = blockIdx.x;
    const int ec = blockIdx.y;
    const int tid = threadIdx.x;

    __shared__ float ws[128];
    if (tid < 128) ws[tid] = g_scores[(size_t)b * TE + ec * 128 + tid];
    __syncthreads();

    const float* eb = enc + (size_t)b * TE * DE + (size_t)ec * 128 * DE;
    float acc[4] = {0.f, 0.f, 0.f, 0.f};
    for (int e = 0; e < 128; e++) {
        float we = ws[e];
        #pragma unroll
        for (int i = 0; i < 4; i++)
            acc[i] += we * eb[(size_t)e * DE + tid + i * 256];
    }
    #pragma unroll
    for (int i = 0; i < 4; i++)
        atomicAdd(&out[(size_t)b * DE + tid + i * 256], acc[i]);
}

// ---------------------------------------------------------------------------
extern "C" void kernel_launch(void* const* d_in, const int* in_sizes, int n_in,
                              void* d_out, int out_size) {
    const float* enc  = (const float*)d_in[0];
    const float* dec  = (const float*)d_in[1];
    const float* Wa_w = (const float*)d_in[2];
    const float* Wa_b = (const float*)d_in[3];
    const float* Ua_w = (const float*)d_in[4];
    const float* Ua_b = (const float*)d_in[5];
    const float* Va_w = (const float*)d_in[6];
    float* out = (float*)d_out;

    cudaFuncSetAttribute(score_kernel, cudaFuncAttributeMaxDynamicSharedMemorySize, SC_SMEM);

    zero_scores_kernel<<<64, 1024>>>();
    wa_kernel<<<64, 256>>>(dec, Wa_w, Wa_b);
    score_kernel<<<dim3(H / 128, B * TE / 128), 128, SC_SMEM>>>(enc, Ua_w, Ua_b, Va_w);
    softmax_kernel<<<B, 256>>>();
    zero_kernel<<<(B * DE) / 256, 256>>>(out);
    context_kernel<<<dim3(B, 8), 256>>>(enc, out);
}

// round 8
// speedup vs baseline: 4.8481x; 1.1022x over previous
#include <cuda_runtime.h>
#include <math.h>
#include <stdint.h>

#define B   64
#define TE  1024
#define DE  1024
#define DD  1024
#define H   1024

__device__ float g_Wa[B * H];        // Wa[b,h] = dec[b]·Wa_w[h] + Wa_b[h]
__device__ float g_scores[B * TE];   // partial scores -> softmax weights

__device__ __forceinline__ void cp16(uint32_t s, const void* g) {
    asm volatile("cp.async.cg.shared.global [%0], [%1], 16;"
                 :: "r"(s), "l"(__cvta_generic_to_global(g)) : "memory");
}
#define CP_COMMIT() asm volatile("cp.async.commit_group;" ::: "memory")
#define CP_WAIT2()  asm volatile("cp.async.wait_group 2;" ::: "memory")

__device__ __forceinline__ uint32_t smem_u32(const void* p) {
    uint32_t a;
    asm("{ .reg .u64 t; cvta.to.shared.u64 t, %1; cvt.u32.u64 %0, t; }" : "=r"(a) : "l"(p));
    return a;
}

// ---------------------------------------------------------------------------
// K0: zero partial-score accumulator
// ---------------------------------------------------------------------------
__global__ void zero_scores_kernel() {
    g_scores[blockIdx.x * 1024 + threadIdx.x] = 0.f;
}

// ---------------------------------------------------------------------------
// K1: Wa[b,h] = dec[b]·Wa_w[h] + Wa_b[h]   (tiny, fp32 SIMT)
// ---------------------------------------------------------------------------
__global__ void wa_kernel(const float* __restrict__ dec,
                          const float* __restrict__ Wa_w,
                          const float* __restrict__ Wa_b) {
    const int h0 = blockIdx.x * 16;
    const int tid = threadIdx.x;
    const int hl = tid >> 4;
    const int bl = tid & 15;

    __shared__ float sW[16][65];
    __shared__ float sD[64][65];

    float acc[4] = {0.f, 0.f, 0.f, 0.f};

    for (int d0 = 0; d0 < DD; d0 += 64) {
        __syncthreads();
        #pragma unroll
        for (int i = 0; i < 4; i++) {
            int l = tid + i * 256;
            int h = l >> 6, d = l & 63;
            sW[h][d] = Wa_w[(size_t)(h0 + h) * DD + d0 + d];
        }
        #pragma unroll
        for (int i = 0; i < 16; i++) {
            int l = tid + i * 256;
            int b = l >> 6, d = l & 63;
            sD[b][d] = dec[(size_t)b * DD + d0 + d];
        }
        __syncthreads();
        #pragma unroll 8
        for (int d = 0; d < 64; d++) {
            float w = sW[hl][d];
            #pragma unroll
            for (int i = 0; i < 4; i++)
                acc[i] += w * sD[bl + 16 * i][d];
        }
    }
    float bias = Wa_b[h0 + hl];
    #pragma unroll
    for (int i = 0; i < 4; i++)
        g_Wa[(size_t)(bl + 16 * i) * H + h0 + hl] = acc[i] + bias;
}

// ---------------------------------------------------------------------------
// K2: fused Ua-GEMM (mma.sync tf32) + tanh + Va reduction
//   CTA tile: 256 e x 128 h, K=1024 in 32 chunks of 32.
//   8 warps (256 thr) as 4(m) x 2(n); warp tile m64 x n64.
//   4-stage cp.async pipeline, ONE barrier per chunk, XOR-swizzled smem.
//   Stage = A(256x32 fl = 32KB) + B(128x32 fl = 16KB) = 48KB; 4 stages = 192KB.
// ---------------------------------------------------------------------------
#define STG    49152
#define SB_OFF 32768
#define S_WAU  196608
#define S_VAW  197120
#define SC_SMEM 197632

__global__ __launch_bounds__(256, 1)
void score_kernel(const float* __restrict__ enc,
                  const float* __restrict__ Ua_w,
                  const float* __restrict__ Ua_b,
                  const float* __restrict__ Va_w) {
    extern __shared__ char sm[];
    const uint32_t smb = smem_u32(sm);

    const int tid  = threadIdx.x;
    const int wid  = tid >> 5;
    const int lane = tid & 31;
    const int wm = wid >> 1;      // warp rows: wm*64..+63 (of 256)
    const int wn = wid & 1;       // warp cols: wn*64..+63 (of 128)
    const int lq = lane >> 2;     // 0..7
    const int lr = lane & 3;      // 0..3

    const int b  = blockIdx.y >> 2;
    const int e0 = (blockIdx.y & 3) * 256;
    const int h0 = blockIdx.x * 128;

    const char* gA = (const char*)(enc  + ((size_t)b * TE + e0) * DE);
    const char* gB = (const char*)(Ua_w + (size_t)h0 * DE);

    // load geometry: 256 threads; A: 256 rows x 8 16B-chunks (8/thread),
    // B: 128 rows x 8 chunks (4/thread). XOR swizzle: chunk ^ ((row&7)*16).
    const int r0   = tid >> 3;             // 0..31
    const int ci16 = (tid & 7) * 16;       // byte chunk in 128B row
    const uint32_t swz = (uint32_t)((r0 & 7) * 16);
    const uint32_t cswz = (uint32_t)ci16 ^ swz;

    uint32_t aoff[8], boff[4];
    #pragma unroll
    for (int i = 0; i < 8; i++) aoff[i] = (uint32_t)(r0 + 32 * i) * 128 + cswz;
    #pragma unroll
    for (int i = 0; i < 4; i++) boff[i] = SB_OFF + (uint32_t)(r0 + 32 * i) * 128 + cswz;

    const char* gAt = gA + (size_t)r0 * 4096 + ci16;
    const char* gBt = gB + (size_t)r0 * 4096 + ci16;

    // prologue: chunks 0..2 -> stages 0..2
    #pragma unroll
    for (int s = 0; s < 3; s++) {
        const uint32_t base = smb + (uint32_t)s * STG;
        const size_t go = (size_t)s * 128;
        #pragma unroll
        for (int i = 0; i < 8; i++) cp16(base + aoff[i], gAt + (size_t)i * 32 * 4096 + go);
        #pragma unroll
        for (int i = 0; i < 4; i++) cp16(base + boff[i], gBt + (size_t)i * 32 * 4096 + go);
        CP_COMMIT();
    }

    float acc[4][8][4];
    #pragma unroll
    for (int m = 0; m < 4; m++)
        #pragma unroll
        for (int n = 0; n < 8; n++)
            #pragma unroll
            for (int r = 0; r < 4; r++)
                acc[m][n][r] = 0.f;

    const uint32_t lqx = (uint32_t)(lq << 2);

    for (int c = 0; c < 32; c++) {
        CP_WAIT2();            // own chunk-c copies done (2 chunks in flight)
        __syncthreads();       // everyone's chunk-c done; compute(c-1) fully drained
        if (c + 3 < 32) {      // prefetch into stage (c+3)%4 == (c-1)%4 (just freed)
            const uint32_t base = smb + (uint32_t)((c + 3) & 3) * STG;
            const size_t go = (size_t)(c + 3) * 128;
            #pragma unroll
            for (int i = 0; i < 8; i++) cp16(base + aoff[i], gAt + (size_t)i * 32 * 4096 + go);
            #pragma unroll
            for (int i = 0; i < 4; i++) cp16(base + boff[i], gBt + (size_t)i * 32 * 4096 + go);
        }
        CP_COMMIT();

        const uint32_t* Aw = (const uint32_t*)(sm + (size_t)(c & 3) * STG);
        const uint32_t* Bw = (const uint32_t*)(sm + (size_t)(c & 3) * STG + SB_OFF);

        #pragma unroll
        for (int k0 = 0; k0 < 32; k0 += 8) {
            const uint32_t kx0 = ((uint32_t)(k0 + lr))     ^ lqx;
            const uint32_t kx1 = ((uint32_t)(k0 + lr + 4)) ^ lqx;
            uint32_t a[4][4], bb[8][2];
            #pragma unroll
            for (int m = 0; m < 4; m++) {
                const uint32_t r1 = (uint32_t)(wm * 64 + m * 16 + lq) * 32;
                a[m][0] = Aw[r1 + kx0];
                a[m][1] = Aw[r1 + 256 + kx0];
                a[m][2] = Aw[r1 + kx1];
                a[m][3] = Aw[r1 + 256 + kx1];
            }
            #pragma unroll
            for (int n = 0; n < 8; n++) {
                const uint32_t br = (uint32_t)(wn * 64 + n * 8 + lq) * 32;
                bb[n][0] = Bw[br + kx0];
                bb[n][1] = Bw[br + kx1];
            }
            #pragma unroll
            for (int m = 0; m < 4; m++)
                #pragma unroll
                for (int n = 0; n < 8; n++)
                    asm volatile(
                        "mma.sync.aligned.m16n8k8.row.col.f32.tf32.tf32.f32 "
                        "{%0,%1,%2,%3}, {%4,%5,%6,%7}, {%8,%9}, {%0,%1,%2,%3};\n"
                        : "+f"(acc[m][n][0]), "+f"(acc[m][n][1]),
                          "+f"(acc[m][n][2]), "+f"(acc[m][n][3])
                        : "r"(a[m][0]), "r"(a[m][1]), "r"(a[m][2]), "r"(a[m][3]),
                          "r"(bb[n][0]), "r"(bb[n][1]));
        }
    }

    // stage wau/vaw for this h-block
    if (tid < 128) {
        ((float*)(sm + S_WAU))[tid] = g_Wa[(size_t)b * H + h0 + tid] + Ua_b[h0 + tid];
        ((float*)(sm + S_VAW))[tid] = Va_w[h0 + tid];
    }
    __syncthreads();
    const float* wau = (const float*)(sm + S_WAU);
    const float* vaw = (const float*)(sm + S_VAW);

    // epilogue: tanh + Va-weighted reduce -> per-row partial scores
    #pragma unroll
    for (int m = 0; m < 4; m++) {
        float rs[2] = {0.f, 0.f};
        #pragma unroll
        for (int n = 0; n < 8; n++)
            #pragma unroll
            for (int r = 0; r < 4; r++) {
                int h = wn * 64 + n * 8 + 2 * lr + (r & 1);
                rs[r >> 1] += vaw[h] * tanhf(acc[m][n][r] + wau[h]);
            }
        #pragma unroll
        for (int rr = 0; rr < 2; rr++) {
            float s = rs[rr];
            s += __shfl_xor_sync(0xffffffffu, s, 1);
            s += __shfl_xor_sync(0xffffffffu, s, 2);
            if (lr == 0) {
                int e = e0 + wm * 64 + m * 16 + rr * 8 + lq;
                atomicAdd(&g_scores[(size_t)b * TE + e], s);
            }
        }
    }
}

// ---------------------------------------------------------------------------
// K3: softmax over Te per batch (Va_b omitted: softmax shift-invariant)
// ---------------------------------------------------------------------------
__global__ void softmax_kernel() {
    const int b = blockIdx.x;
    const int tid = threadIdx.x;
    float* row = g_scores + (size_t)b * TE;
    __shared__ float red[256];

    float m = -1e30f;
    #pragma unroll
    for (int i = 0; i < 4; i++) m = fmaxf(m, row[tid + i * 256]);
    red[tid] = m;
    __syncthreads();
    for (int s = 128; s > 0; s >>= 1) {
        if (tid < s) red[tid] = fmaxf(red[tid], red[tid + s]);
        __syncthreads();
    }
    float M = red[0];
    __syncthreads();

    float vals[4];
    float sum = 0.f;
    #pragma unroll
    for (int i = 0; i < 4; i++) {
        vals[i] = expf(row[tid + i * 256] - M);
        sum += vals[i];
    }
    red[tid] = sum;
    __syncthreads();
    for (int s = 128; s > 0; s >>= 1) {
        if (tid < s) red[tid] += red[tid + s];
        __syncthreads();
    }
    float inv = 1.f / red[0];
    #pragma unroll
    for (int i = 0; i < 4; i++) row[tid + i * 256] = vals[i] * inv;
}

// ---------------------------------------------------------------------------
// K4: context[b,d] = sum_e w[b,e] * enc[b,e,d]
// ---------------------------------------------------------------------------
__global__ void zero_kernel(float* __restrict__ out) {
    out[blockIdx.x * 256 + threadIdx.x] = 0.f;
}

__global__ void context_kernel(const float* __restrict__ enc,
                               float* __restrict__ out) {
    const int b  = blockIdx.x;
    const int ec = blockIdx.y;
    const int tid = threadIdx.x;

    __shared__ float ws[128];
    if (tid < 128) ws[tid] = g_scores[(size_t)b * TE + ec * 128 + tid];
    __syncthreads();

    const float* eb = enc + (size_t)b * TE * DE + (size_t)ec * 128 * DE;
    float acc[4] = {0.f, 0.f, 0.f, 0.f};
    for (int e = 0; e < 128; e++) {
        float we = ws[e];
        #pragma unroll
        for (int i = 0; i < 4; i++)
            acc[i] += we * eb[(size_t)e * DE + tid + i * 256];
    }
    #pragma unroll
    for (int i = 0; i < 4; i++)
        atomicAdd(&out[(size_t)b * DE + tid + i * 256], acc[i]);
}

// ---------------------------------------------------------------------------
extern "C" void kernel_launch(void* const* d_in, const int* in_sizes, int n_in,
                              void* d_out, int out_size) {
    const float* enc  = (const float*)d_in[0];
    const float* dec  = (const float*)d_in[1];
    const float* Wa_w = (const float*)d_in[2];
    const float* Wa_b = (const float*)d_in[3];
    const float* Ua_w = (const float*)d_in[4];
    const float* Ua_b = (const float*)d_in[5];
    const float* Va_w = (const float*)d_in[6];
    float* out = (float*)d_out;

    cudaFuncSetAttribute(score_kernel, cudaFuncAttributeMaxDynamicSharedMemorySize, SC_SMEM);

    zero_scores_kernel<<<64, 1024>>>();
    wa_kernel<<<64, 256>>>(dec, Wa_w, Wa_b);
    score_kernel<<<dim3(H / 128, B * TE / 256), 256, SC_SMEM>>>(enc, Ua_w, Ua_b, Va_w);
    softmax_kernel<<<B, 256>>>();
    zero_kernel<<<(B * DE) / 256, 256>>>(out);
    context_kernel<<<dim3(B, 8), 256>>>(enc, out);
}